// round 9
// baseline (speedup 1.0000x reference)
#include <cuda_runtime.h>
#include <cuda_bf16.h>
#include <cstdint>
#include <math.h>

#define SEQ    3072
#define HID    1536
#define NH     12
#define HD     128
#define QKVW   4608   // 3*HID
#define INTER  13696
#define MAXL   1024
#define EPS    1e-6f

// ===================== PTX helpers (baseline PTX only) ======================
__device__ __forceinline__ uint32_t smem_to_u32(const void* p) {
    uint32_t a;
    asm("{ .reg .u64 t; cvta.to.shared.u64 t, %1; cvt.u32.u64 %0, t; }"
        : "=r"(a) : "l"(p));
    return a;
}
__device__ __forceinline__ void cp_async16(uint32_t dst, const void* src) {
    asm volatile("cp.async.cg.shared.global [%0], [%1], 16;"
                 :: "r"(dst), "l"(src) : "memory");
}
#define CP_COMMIT() asm volatile("cp.async.commit_group;" ::: "memory")
#define CP_WAIT2()  asm volatile("cp.async.wait_group 2;" ::: "memory")
#define CP_WAIT1()  asm volatile("cp.async.wait_group 1;" ::: "memory")
#define CP_WAIT0()  asm volatile("cp.async.wait_group 0;" ::: "memory")

__device__ __forceinline__ void ldsm4(uint32_t* r, uint32_t addr) {
    asm volatile("ldmatrix.sync.aligned.m8n8.x4.shared.b16 {%0,%1,%2,%3}, [%4];"
                 : "=r"(r[0]), "=r"(r[1]), "=r"(r[2]), "=r"(r[3]) : "r"(addr));
}
__device__ __forceinline__ void ldsm2(uint32_t* r, uint32_t addr) {
    asm volatile("ldmatrix.sync.aligned.m8n8.x2.shared.b16 {%0,%1}, [%2];"
                 : "=r"(r[0]), "=r"(r[1]) : "r"(addr));
}
__device__ __forceinline__ void ldsm2t(uint32_t* r, uint32_t addr) {
    asm volatile("ldmatrix.sync.aligned.m8n8.x2.trans.shared.b16 {%0,%1}, [%2];"
                 : "=r"(r[0]), "=r"(r[1]) : "r"(addr));
}
__device__ __forceinline__ void mma_bf16(float* c, const uint32_t* a, const uint32_t* b) {
    asm volatile("mma.sync.aligned.m16n8k16.row.col.f32.bf16.bf16.f32 "
                 "{%0,%1,%2,%3}, {%4,%5,%6,%7}, {%8,%9}, {%0,%1,%2,%3};"
                 : "+f"(c[0]), "+f"(c[1]), "+f"(c[2]), "+f"(c[3])
                 : "r"(a[0]), "r"(a[1]), "r"(a[2]), "r"(a[3]),
                   "r"(b[0]), "r"(b[1]));
}
__device__ __forceinline__ void split_bf16(float v, __nv_bfloat16& h, __nv_bfloat16& l) {
    h = __float2bfloat16(v);
    l = __float2bfloat16(v - __bfloat162float(h));
}
// swizzle for 64B-row tiles (128 rows x 32 bf16)
__device__ __forceinline__ uint32_t sw32(uint32_t off) {
    return off ^ ((off >> 3) & 0x30);
}
// swizzle for 256B-row tiles (V)
__device__ __forceinline__ uint32_t sw128(uint32_t off) {
    return off ^ ((off >> 3) & 0x70);
}

// stage layout: Ah@0, Al@8K, Bh@16K, Bl@24K ; stage stride 32KB; 3 stages
#define STAGE   32768
#define NSTAGE  3
#define GEMM_SMEM (NSTAGE * STAGE)

// ===================== scratch =============================================
__device__ float g_qkv   [SEQ * QKVW];
__device__ float g_scores[(size_t)NH * SEQ * MAXL];
__device__ float g_hid2  [SEQ * HID];
__device__ float g_up    [(size_t)SEQ * INTER];

__device__ __nv_bfloat16 g_hn_h [SEQ * HID],  g_hn_l [SEQ * HID];
__device__ __nv_bfloat16 g_h2n_h[SEQ * HID],  g_h2n_l[SEQ * HID];
__device__ __nv_bfloat16 g_at_h [SEQ * HID],  g_at_l [SEQ * HID];
__device__ __nv_bfloat16 g_act_h[(size_t)SEQ * INTER], g_act_l[(size_t)SEQ * INTER];

__device__ __nv_bfloat16 g_q_h[(size_t)NH * SEQ * HD], g_q_l[(size_t)NH * SEQ * HD];
__device__ __nv_bfloat16 g_k_h[(size_t)NH * SEQ * HD], g_k_l[(size_t)NH * SEQ * HD];
__device__ __nv_bfloat16 g_v_h[(size_t)NH * SEQ * HD], g_v_l[(size_t)NH * SEQ * HD];
__device__ __nv_bfloat16 g_p_h[(size_t)NH * SEQ * MAXL], g_p_l[(size_t)NH * SEQ * MAXL];

__device__ __nv_bfloat16 g_wqkv_h [(size_t)QKVW * HID],  g_wqkv_l [(size_t)QKVW * HID];
__device__ __nv_bfloat16 g_wproj_h[(size_t)HID * HID],   g_wproj_l[(size_t)HID * HID];
__device__ __nv_bfloat16 g_wgate_h[(size_t)INTER * HID], g_wgate_l[(size_t)INTER * HID];
__device__ __nv_bfloat16 g_wup_h  [(size_t)INTER * HID], g_wup_l  [(size_t)INTER * HID];
__device__ __nv_bfloat16 g_wdown_h[(size_t)HID * INTER], g_wdown_l[(size_t)HID * INTER];

// ===================== weight transpose + split =============================
__global__ void wconv_t(const float* __restrict__ W, __nv_bfloat16* __restrict__ Th,
                        __nv_bfloat16* __restrict__ Tl, int K, int N) {
    __shared__ float ts[32][33];
    int n0 = blockIdx.x * 32, k0 = blockIdx.y * 32;
    int tx = threadIdx.x, ty = threadIdx.y;   // 32 x 8
#pragma unroll
    for (int r = 0; r < 32; r += 8)
        ts[ty + r][tx] = W[(size_t)(k0 + ty + r) * N + n0 + tx];
    __syncthreads();
#pragma unroll
    for (int r = 0; r < 32; r += 8) {
        float v = ts[tx][ty + r];
        __nv_bfloat16 h, l;
        split_bf16(v, h, l);
        size_t o = (size_t)(n0 + ty + r) * K + k0 + tx;
        Th[o] = h;
        Tl[o] = l;
    }
}

// ===================== k=32 chunk machinery ================================
// load A[128 x 32] hi/lo + B[128 x 32] hi/lo (64B rows, sw32)
__device__ __forceinline__ void load_chunk32(
    uint32_t buf, int tid,
    const __nv_bfloat16* __restrict__ Ah, const __nv_bfloat16* __restrict__ Al,
    const __nv_bfloat16* __restrict__ Bh, const __nv_bfloat16* __restrict__ Bl,
    int m0, int n0, int k0, int K) {
#pragma unroll
    for (int t = 0; t < 8; t++) {
        int idx = tid + t * 256;            // 0..2047
        int tile = idx >> 9;                // 512 x 16B units per tile
        int u = idx & 511;
        int r = u >> 2, j = u & 3;
        const __nv_bfloat16* src =
            (tile == 0 ? Ah : tile == 1 ? Al : tile == 2 ? Bh : Bl);
        int row = (tile < 2 ? m0 : n0) + r;
        uint32_t dst = buf + tile * 8192 + sw32((uint32_t)(r * 64 + j * 16));
        cp_async16(dst, src + (size_t)row * K + k0 + j * 8);
    }
}

// compute on one k=32 chunk (both operands [row][k], 64B rows)
__device__ __forceinline__ void compute_chunk32(
    uint32_t buf, int wm, int wn, int lane, float acc[4][4][4]) {
    const uint32_t bAh = buf;
    const uint32_t bAl = buf + 8192;
    const uint32_t bBh = buf + 16384;
    const uint32_t bBl = buf + 24576;
#pragma unroll
    for (int ks = 0; ks < 2; ks++) {
        uint32_t bh[4][2], bl[4][2];
#pragma unroll
        for (int ni = 0; ni < 4; ni++) {
            uint32_t rowB = wn * 32 + ni * 8 + (lane & 7);
            uint32_t kb = ks * 32 + ((lane >> 3) & 1) * 16;
            uint32_t sw = sw32(rowB * 64 + kb);
            ldsm2(bh[ni], bBh + sw);
            ldsm2(bl[ni], bBl + sw);
        }
#pragma unroll
        for (int mi = 0; mi < 4; mi++) {
            uint32_t rowA = wm * 64 + mi * 16 + (lane & 15);
            uint32_t kb = ks * 32 + (lane >> 4) * 16;
            uint32_t sw = sw32(rowA * 64 + kb);
            uint32_t ah[4], al[4];
            ldsm4(ah, bAh + sw);
            ldsm4(al, bAl + sw);
#pragma unroll
            for (int ni = 0; ni < 4; ni++) {
                mma_bf16(acc[mi][ni], ah, bh[ni]);
                mma_bf16(acc[mi][ni], ah, bl[ni]);
                mma_bf16(acc[mi][ni], al, bh[ni]);
            }
        }
    }
}

// ===================== main GEMM (fp32 / residual / fused swiglu) ==========
__global__ __launch_bounds__(256, 2) void gemm_bf16x3(
    const __nv_bfloat16* __restrict__ Ah, const __nv_bfloat16* __restrict__ Al,
    const __nv_bfloat16* __restrict__ Bh, const __nv_bfloat16* __restrict__ Bl,
    const float* __restrict__ R, float* __restrict__ C,
    const float* __restrict__ Up,
    __nv_bfloat16* __restrict__ Oh, __nv_bfloat16* __restrict__ Ol,
    int N, int K) {
    extern __shared__ char smem[];
    const uint32_t sb = smem_to_u32(smem);
    const int tid = threadIdx.x;
    const int wid = tid >> 5;
    const int lane = tid & 31;
    const int wm = wid & 1;
    const int wn = wid >> 1;
    const int m0 = blockIdx.x * 128;
    const int n0 = blockIdx.y * 128;

    float acc[4][4][4];
#pragma unroll
    for (int i = 0; i < 4; i++)
#pragma unroll
        for (int j = 0; j < 4; j++)
#pragma unroll
            for (int k = 0; k < 4; k++) acc[i][j][k] = 0.f;

    const int nch = K >> 5;
    load_chunk32(sb, tid, Ah, Al, Bh, Bl, m0, n0, 0, K);
    CP_COMMIT();
    load_chunk32(sb + STAGE, tid, Ah, Al, Bh, Bl, m0, n0, 32, K);
    CP_COMMIT();

    int st = 0;
    for (int i = 0; i < nch; i++) {
        if (i + 2 < nch) {
            int ld = (st + 2 >= NSTAGE) ? st + 2 - NSTAGE : st + 2;
            load_chunk32(sb + ld * STAGE, tid, Ah, Al, Bh, Bl, m0, n0, (i + 2) << 5, K);
            CP_COMMIT();
            CP_WAIT2();
        } else if (i + 1 < nch) {
            CP_WAIT1();
        } else {
            CP_WAIT0();
        }
        __syncthreads();
        compute_chunk32(sb + st * STAGE, wm, wn, lane, acc);
        __syncthreads();
        if (++st == NSTAGE) st = 0;
    }

    const int gr = lane >> 2;
    const int gc = (lane & 3) * 2;
#pragma unroll
    for (int mi = 0; mi < 4; mi++) {
        int r0 = m0 + wm * 64 + mi * 16 + gr;
#pragma unroll
        for (int ni = 0; ni < 4; ni++) {
            int c = n0 + wn * 32 + ni * 8 + gc;
            size_t o0 = (size_t)r0 * N + c;
            size_t o1 = (size_t)(r0 + 8) * N + c;
            if (Oh) {   // fused swiglu: acc = gate pre-act
                float2 u0 = *(const float2*)(Up + o0);
                float2 u1 = *(const float2*)(Up + o1);
                float g, v;
                __nv_bfloat16 h, l;
                g = acc[mi][ni][0]; v = (g / (1.f + expf(-g))) * u0.x;
                split_bf16(v, h, l); Oh[o0] = h; Ol[o0] = l;
                g = acc[mi][ni][1]; v = (g / (1.f + expf(-g))) * u0.y;
                split_bf16(v, h, l); Oh[o0 + 1] = h; Ol[o0 + 1] = l;
                g = acc[mi][ni][2]; v = (g / (1.f + expf(-g))) * u1.x;
                split_bf16(v, h, l); Oh[o1] = h; Ol[o1] = l;
                g = acc[mi][ni][3]; v = (g / (1.f + expf(-g))) * u1.y;
                split_bf16(v, h, l); Oh[o1 + 1] = h; Ol[o1 + 1] = l;
            } else {
                float2 v0 = make_float2(acc[mi][ni][0], acc[mi][ni][1]);
                float2 v1 = make_float2(acc[mi][ni][2], acc[mi][ni][3]);
                if (R) {
                    float2 rr0 = *(const float2*)(R + o0);
                    float2 rr1 = *(const float2*)(R + o1);
                    v0.x += rr0.x; v0.y += rr0.y;
                    v1.x += rr1.x; v1.y += rr1.y;
                }
                *(float2*)(C + o0) = v0;
                *(float2*)(C + o1) = v1;
            }
        }
    }
}

// ===================== attention QK^T =======================================
__global__ __launch_bounds__(256, 2) void attn_qk(
    const __nv_bfloat16* __restrict__ Qh, const __nv_bfloat16* __restrict__ Ql,
    const __nv_bfloat16* __restrict__ Kh, const __nv_bfloat16* __restrict__ Kl,
    const int* __restrict__ cu, int nseg, float* __restrict__ scores) {
    extern __shared__ char smem[];
    const uint32_t sb = smem_to_u32(smem);
    const int h = blockIdx.z / nseg, s = blockIdx.z % nseg;
    const int s0 = cu[s];
    const int L = cu[s + 1] - s0;
    const int q0 = blockIdx.y * 128, kt0 = blockIdx.x * 128;
    if (q0 >= L || kt0 >= L) return;
    const int tid = threadIdx.x;
    const int wid = tid >> 5, lane = tid & 31;
    const int wm = wid & 1, wn = wid >> 1;

    const __nv_bfloat16* qh = Qh + ((size_t)h * SEQ + s0 + q0) * HD;
    const __nv_bfloat16* ql = Ql + ((size_t)h * SEQ + s0 + q0) * HD;
    const __nv_bfloat16* kh = Kh + ((size_t)h * SEQ + s0 + kt0) * HD;
    const __nv_bfloat16* kl = Kl + ((size_t)h * SEQ + s0 + kt0) * HD;

    float acc[4][4][4];
#pragma unroll
    for (int i = 0; i < 4; i++)
#pragma unroll
        for (int j = 0; j < 4; j++)
#pragma unroll
            for (int k = 0; k < 4; k++) acc[i][j][k] = 0.f;

    const int nch = HD >> 5;    // 4
    load_chunk32(sb, tid, qh, ql, kh, kl, 0, 0, 0, HD);
    CP_COMMIT();
    load_chunk32(sb + STAGE, tid, qh, ql, kh, kl, 0, 0, 32, HD);
    CP_COMMIT();
    int st = 0;
    for (int i = 0; i < nch; i++) {
        if (i + 2 < nch) {
            int ld = (st + 2 >= NSTAGE) ? st + 2 - NSTAGE : st + 2;
            load_chunk32(sb + ld * STAGE, tid, qh, ql, kh, kl, 0, 0, (i + 2) << 5, HD);
            CP_COMMIT();
            CP_WAIT2();
        } else if (i + 1 < nch) {
            CP_WAIT1();
        } else {
            CP_WAIT0();
        }
        __syncthreads();
        compute_chunk32(sb + st * STAGE, wm, wn, lane, acc);
        __syncthreads();
        if (++st == NSTAGE) st = 0;
    }

    const float scale = 0.088388347648318447f;
    const int gr = lane >> 2;
    const int gc = (lane & 3) * 2;
#pragma unroll
    for (int mi = 0; mi < 4; mi++) {
        int qg = s0 + q0 + wm * 64 + mi * 16 + gr;
#pragma unroll
        for (int ni = 0; ni < 4; ni++) {
            int c = kt0 + wn * 32 + ni * 8 + gc;
            size_t o0 = ((size_t)h * SEQ + qg) * MAXL + c;
            size_t o1 = ((size_t)h * SEQ + qg + 8) * MAXL + c;
            *(float2*)(scores + o0) =
                make_float2(acc[mi][ni][0] * scale, acc[mi][ni][1] * scale);
            *(float2*)(scores + o1) =
                make_float2(acc[mi][ni][2] * scale, acc[mi][ni][3] * scale);
        }
    }
}

// ===================== softmax -> P hi/lo bf16 ==============================
__global__ void softmax_psplit(float* __restrict__ scores,
                               const int* __restrict__ cu, int nseg,
                               __nv_bfloat16* __restrict__ ph,
                               __nv_bfloat16* __restrict__ pl) {
    int row = blockIdx.x;
    int q = row % SEQ;
    int L = MAXL;
    for (int s = 0; s < nseg; s++)
        if (q >= cu[s] && q < cu[s + 1]) { L = cu[s + 1] - cu[s]; break; }
    float* r = scores + (size_t)row * MAXL;
    int tid = threadIdx.x;
    __shared__ float red[256];
    float m = -3.4e38f;
    for (int i = tid; i < L; i += 256) m = fmaxf(m, r[i]);
    red[tid] = m;
    __syncthreads();
    for (int s = 128; s > 0; s >>= 1) {
        if (tid < s) red[tid] = fmaxf(red[tid], red[tid + s]);
        __syncthreads();
    }
    m = red[0];
    __syncthreads();
    float sum = 0.f;
    for (int i = tid; i < L; i += 256) {
        float e = expf(r[i] - m);
        r[i] = e;
        sum += e;
    }
    red[tid] = sum;
    __syncthreads();
    for (int s = 128; s > 0; s >>= 1) {
        if (tid < s) red[tid] += red[tid + s];
        __syncthreads();
    }
    float inv = 1.f / red[0];
    for (int i = tid; i < L; i += 256) {
        float p = r[i] * inv;
        __nv_bfloat16 hh, ll;
        split_bf16(p, hh, ll);
        ph[(size_t)row * MAXL + i] = hh;
        pl[(size_t)row * MAXL + i] = ll;
    }
}

// ===================== attention P@V ========================================
// P tiles 128q x 32k (64B rows, sw32); V tiles 32k x 128d (256B rows, sw128)
__device__ __forceinline__ void load_chunk32_pv(
    uint32_t buf, int tid,
    const __nv_bfloat16* __restrict__ Ph, const __nv_bfloat16* __restrict__ Pl,
    const __nv_bfloat16* __restrict__ Vh, const __nv_bfloat16* __restrict__ Vl,
    int k0) {
#pragma unroll
    for (int t = 0; t < 8; t++) {
        int idx = tid + t * 256;
        int tile = idx >> 9;
        int u = idx & 511;
        if (tile < 2) {
            int r = u >> 2, j = u & 3;
            const __nv_bfloat16* src = (tile == 0) ? Ph : Pl;
            uint32_t dst = buf + tile * 8192 + sw32((uint32_t)(r * 64 + j * 16));
            cp_async16(dst, src + (size_t)r * MAXL + k0 + j * 8);
        } else {
            int r = u >> 4, c = u & 15;     // 32 rows x 16 units
            const __nv_bfloat16* src = (tile == 2) ? Vh : Vl;
            uint32_t dst = buf + tile * 8192 + sw128((uint32_t)(r * 256 + c * 16));
            cp_async16(dst, src + (size_t)(k0 + r) * HD + c * 8);
        }
    }
}

__global__ __launch_bounds__(256, 2) void attn_pv_mma(
    const __nv_bfloat16* __restrict__ Ph, const __nv_bfloat16* __restrict__ Pl,
    const __nv_bfloat16* __restrict__ Vh, const __nv_bfloat16* __restrict__ Vl,
    const int* __restrict__ cu, int nseg,
    __nv_bfloat16* __restrict__ oh, __nv_bfloat16* __restrict__ ol) {
    extern __shared__ char smem[];
    const uint32_t sb = smem_to_u32(smem);
    const int h = blockIdx.z / nseg, s = blockIdx.z % nseg;
    const int s0 = cu[s];
    const int L = cu[s + 1] - s0;
    const int q0 = blockIdx.y * 128;
    if (q0 >= L) return;
    const int tid = threadIdx.x;
    const int wid = tid >> 5, lane = tid & 31;
    const int wm = wid & 1, wn = wid >> 1;

    const __nv_bfloat16* ph = Ph + ((size_t)h * SEQ + s0 + q0) * MAXL;
    const __nv_bfloat16* pl = Pl + ((size_t)h * SEQ + s0 + q0) * MAXL;
    const __nv_bfloat16* vh = Vh + ((size_t)h * SEQ + s0) * HD;
    const __nv_bfloat16* vl = Vl + ((size_t)h * SEQ + s0) * HD;

    float acc[4][4][4];
#pragma unroll
    for (int i = 0; i < 4; i++)
#pragma unroll
        for (int j = 0; j < 4; j++)
#pragma unroll
            for (int k = 0; k < 4; k++) acc[i][j][k] = 0.f;

    const int nch = L >> 5;
    load_chunk32_pv(sb, tid, ph, pl, vh, vl, 0);
    CP_COMMIT();
    load_chunk32_pv(sb + STAGE, tid, ph, pl, vh, vl, 32);
    CP_COMMIT();
    int st = 0;
    for (int i = 0; i < nch; i++) {
        if (i + 2 < nch) {
            int ld = (st + 2 >= NSTAGE) ? st + 2 - NSTAGE : st + 2;
            load_chunk32_pv(sb + ld * STAGE, tid, ph, pl, vh, vl, (i + 2) << 5);
            CP_COMMIT();
            CP_WAIT2();
        } else if (i + 1 < nch) {
            CP_WAIT1();
        } else {
            CP_WAIT0();
        }
        __syncthreads();
        {
            const uint32_t buf = sb + st * STAGE;
            const uint32_t bAh = buf;
            const uint32_t bAl = buf + 8192;
            const uint32_t bBh = buf + 16384;
            const uint32_t bBl = buf + 24576;
#pragma unroll
            for (int ks = 0; ks < 2; ks++) {
                uint32_t bh[4][2], bl[4][2];
#pragma unroll
                for (int ni = 0; ni < 4; ni++) {
                    uint32_t nb = (wn * 32 + ni * 8) * 2;
                    uint32_t sw = sw128((ks * 16 + (lane & 15)) * 256 + nb);
                    ldsm2t(bh[ni], bBh + sw);
                    ldsm2t(bl[ni], bBl + sw);
                }
#pragma unroll
                for (int mi = 0; mi < 4; mi++) {
                    uint32_t rowA = wm * 64 + mi * 16 + (lane & 15);
                    uint32_t kb = ks * 32 + (lane >> 4) * 16;
                    uint32_t sw = sw32(rowA * 64 + kb);
                    uint32_t ah[4], al[4];
                    ldsm4(ah, bAh + sw);
                    ldsm4(al, bAl + sw);
#pragma unroll
                    for (int ni = 0; ni < 4; ni++) {
                        mma_bf16(acc[mi][ni], ah, bh[ni]);
                        mma_bf16(acc[mi][ni], ah, bl[ni]);
                        mma_bf16(acc[mi][ni], al, bh[ni]);
                    }
                }
            }
        }
        __syncthreads();
        if (++st == NSTAGE) st = 0;
    }

    const int gr = lane >> 2;
    const int gc = (lane & 3) * 2;
#pragma unroll
    for (int mi = 0; mi < 4; mi++) {
        int qg = s0 + q0 + wm * 64 + mi * 16 + gr;
#pragma unroll
        for (int ni = 0; ni < 4; ni++) {
            int d = wn * 32 + ni * 8 + gc;
            size_t o0 = (size_t)qg * HID + h * HD + d;
            size_t o1 = (size_t)(qg + 8) * HID + h * HD + d;
            __nv_bfloat16 hh, ll;
            split_bf16(acc[mi][ni][0], hh, ll); oh[o0] = hh; ol[o0] = ll;
            split_bf16(acc[mi][ni][1], hh, ll); oh[o0 + 1] = hh; ol[o0 + 1] = ll;
            split_bf16(acc[mi][ni][2], hh, ll); oh[o1] = hh; ol[o1] = ll;
            split_bf16(acc[mi][ni][3], hh, ll); oh[o1 + 1] = hh; ol[o1 + 1] = ll;
        }
    }
}

// ===================== RMSNorm -> bf16 hi/lo ================================
__global__ void rmsnorm_split(const float* __restrict__ x, const float* __restrict__ w,
                              __nv_bfloat16* __restrict__ yh, __nv_bfloat16* __restrict__ yl) {
    int row = blockIdx.x;
    const float* xr = x + (size_t)row * HID;
    int tid = threadIdx.x;
    float ss = 0.f;
    for (int i = tid; i < HID; i += 256) { float v = xr[i]; ss += v * v; }
    __shared__ float red[256];
    red[tid] = ss;
    __syncthreads();
    for (int s = 128; s > 0; s >>= 1) {
        if (tid < s) red[tid] += red[tid + s];
        __syncthreads();
    }
    float inv = rsqrtf(red[0] / (float)HID + EPS);
    for (int i = tid; i < HID; i += 256) {
        float v = xr[i] * inv * w[i];
        __nv_bfloat16 h, l;
        split_bf16(v, h, l);
        yh[(size_t)row * HID + i] = h;
        yl[(size_t)row * HID + i] = l;
    }
}

// ===================== RoPE + per-head split ================================
__global__ void rope_split(const float* __restrict__ qkv, const float* __restrict__ rot,
                           __nv_bfloat16* __restrict__ qh, __nv_bfloat16* __restrict__ ql,
                           __nv_bfloat16* __restrict__ kh, __nv_bfloat16* __restrict__ kl,
                           __nv_bfloat16* __restrict__ vh, __nv_bfloat16* __restrict__ vl) {
    int n = blockIdx.x, h = blockIdx.y, d = threadIdx.x;
    float ang = rot[n * HD + d];
    float c = cosf(ang), s = sinf(ang);
    const float* q = qkv + (size_t)n * QKVW + h * HD;
    const float* k = q + HID;
    const float* v = q + 2 * HID;
    int p = (d < 64) ? d + 64 : d - 64;
    float sgn = (d < 64) ? -1.f : 1.f;
    float qr = q[d] * c + sgn * q[p] * s;
    float kr = k[d] * c + sgn * k[p] * s;
    float vv = v[d];
    size_t o = ((size_t)h * SEQ + n) * HD + d;
    __nv_bfloat16 hh, ll;
    split_bf16(qr, hh, ll); qh[o] = hh; ql[o] = ll;
    split_bf16(kr, hh, ll); kh[o] = hh; kl[o] = ll;
    split_bf16(vv, hh, ll); vh[o] = hh; vl[o] = ll;
}

// ===================== host orchestration ===================================
extern "C" void kernel_launch(void* const* d_in, const int* in_sizes, int n_in,
                              void* d_out, int out_size) {
    const float* hidden = (const float*)d_in[0];
    const float* rot    = (const float*)d_in[1];
    const float* n1w    = (const float*)d_in[2];
    const float* n2w    = (const float*)d_in[3];
    const float* qkv_w  = (const float*)d_in[4];
    const float* proj_w = (const float*)d_in[5];
    const float* gate_w = (const float*)d_in[6];
    const float* up_w   = (const float*)d_in[7];
    const float* down_w = (const float*)d_in[8];
    const int*   cu     = (const int*)d_in[9];
    float* out = (float*)d_out;
    int nseg = in_sizes[9] - 1;

    cudaFuncSetAttribute(gemm_bf16x3, cudaFuncAttributeMaxDynamicSharedMemorySize, GEMM_SMEM);
    cudaFuncSetAttribute(attn_qk, cudaFuncAttributeMaxDynamicSharedMemorySize, GEMM_SMEM);
    cudaFuncSetAttribute(attn_pv_mma, cudaFuncAttributeMaxDynamicSharedMemorySize, GEMM_SMEM);

    float *p_qkv, *p_scores, *p_hid2, *p_up;
    cudaGetSymbolAddress((void**)&p_qkv,    g_qkv);
    cudaGetSymbolAddress((void**)&p_scores, g_scores);
    cudaGetSymbolAddress((void**)&p_hid2,   g_hid2);
    cudaGetSymbolAddress((void**)&p_up,     g_up);
    __nv_bfloat16 *hn_h, *hn_l, *h2n_h, *h2n_l, *at_h, *at_l, *act_h, *act_l;
    __nv_bfloat16 *q_h, *q_l, *k_h, *k_l, *v_h, *v_l, *pp_h, *pp_l;
    __nv_bfloat16 *wq_h, *wq_l, *wp_h, *wp_l, *wg_h, *wg_l, *wu_h, *wu_l, *wd_h, *wd_l;
    cudaGetSymbolAddress((void**)&hn_h, g_hn_h);   cudaGetSymbolAddress((void**)&hn_l, g_hn_l);
    cudaGetSymbolAddress((void**)&h2n_h, g_h2n_h); cudaGetSymbolAddress((void**)&h2n_l, g_h2n_l);
    cudaGetSymbolAddress((void**)&at_h, g_at_h);   cudaGetSymbolAddress((void**)&at_l, g_at_l);
    cudaGetSymbolAddress((void**)&act_h, g_act_h); cudaGetSymbolAddress((void**)&act_l, g_act_l);
    cudaGetSymbolAddress((void**)&q_h, g_q_h);     cudaGetSymbolAddress((void**)&q_l, g_q_l);
    cudaGetSymbolAddress((void**)&k_h, g_k_h);     cudaGetSymbolAddress((void**)&k_l, g_k_l);
    cudaGetSymbolAddress((void**)&v_h, g_v_h);     cudaGetSymbolAddress((void**)&v_l, g_v_l);
    cudaGetSymbolAddress((void**)&pp_h, g_p_h);    cudaGetSymbolAddress((void**)&pp_l, g_p_l);
    cudaGetSymbolAddress((void**)&wq_h, g_wqkv_h); cudaGetSymbolAddress((void**)&wq_l, g_wqkv_l);
    cudaGetSymbolAddress((void**)&wp_h, g_wproj_h);cudaGetSymbolAddress((void**)&wp_l, g_wproj_l);
    cudaGetSymbolAddress((void**)&wg_h, g_wgate_h);cudaGetSymbolAddress((void**)&wg_l, g_wgate_l);
    cudaGetSymbolAddress((void**)&wu_h, g_wup_h);  cudaGetSymbolAddress((void**)&wu_l, g_wup_l);
    cudaGetSymbolAddress((void**)&wd_h, g_wdown_h);cudaGetSymbolAddress((void**)&wd_l, g_wdown_l);

    dim3 tb(32, 8);
    wconv_t<<<dim3(QKVW / 32, HID / 32), tb>>>(qkv_w, wq_h, wq_l, HID, QKVW);
    wconv_t<<<dim3(HID / 32, HID / 32), tb>>>(proj_w, wp_h, wp_l, HID, HID);
    wconv_t<<<dim3(INTER / 32, HID / 32), tb>>>(gate_w, wg_h, wg_l, HID, INTER);
    wconv_t<<<dim3(INTER / 32, HID / 32), tb>>>(up_w, wu_h, wu_l, HID, INTER);
    wconv_t<<<dim3(HID / 32, INTER / 32), tb>>>(down_w, wd_h, wd_l, INTER, HID);

    // 1. norm1
    rmsnorm_split<<<SEQ, 256>>>(hidden, n1w, hn_h, hn_l);
    // 2. qkv
    gemm_bf16x3<<<dim3(SEQ / 128, QKVW / 128), 256, GEMM_SMEM>>>(
        hn_h, hn_l, wq_h, wq_l, nullptr, p_qkv, nullptr, nullptr, nullptr, QKVW, HID);
    // 3. rope + per-head bf16 split
    rope_split<<<dim3(SEQ, NH), HD>>>(p_qkv, rot, q_h, q_l, k_h, k_l, v_h, v_l);
    // 4. scores (tensor core)
    attn_qk<<<dim3(MAXL / 128, MAXL / 128, NH * nseg), 256, GEMM_SMEM>>>(
        q_h, q_l, k_h, k_l, cu, nseg, p_scores);
    // 5. softmax -> P hi/lo
    softmax_psplit<<<NH * SEQ, 256>>>(p_scores, cu, nseg, pp_h, pp_l);
    // 6. O = P @ V (tensor core), writes at hi/lo
    attn_pv_mma<<<dim3(1, MAXL / 128, NH * nseg), 256, GEMM_SMEM>>>(
        pp_h, pp_l, v_h, v_l, cu, nseg, at_h, at_l);
    // 7. hid2 = attn @ proj_w + hidden
    gemm_bf16x3<<<dim3(SEQ / 128, HID / 128), 256, GEMM_SMEM>>>(
        at_h, at_l, wp_h, wp_l, hidden, p_hid2, nullptr, nullptr, nullptr, HID, HID);
    // 8. norm2
    rmsnorm_split<<<SEQ, 256>>>(p_hid2, n2w, h2n_h, h2n_l);
    // 9. up (fp32 out)
    gemm_bf16x3<<<dim3(SEQ / 128, INTER / 128), 256, GEMM_SMEM>>>(
        h2n_h, h2n_l, wu_h, wu_l, nullptr, p_up, nullptr, nullptr, nullptr, INTER, HID);
    // 10. gate + fused swiglu -> act hi/lo
    gemm_bf16x3<<<dim3(SEQ / 128, INTER / 128), 256, GEMM_SMEM>>>(
        h2n_h, h2n_l, wg_h, wg_l, nullptr, nullptr, p_up, act_h, act_l, INTER, HID);
    // 11. out = act @ down_w + hid2
    gemm_bf16x3<<<dim3(SEQ / 128, HID / 128), 256, GEMM_SMEM>>>(
        act_h, act_l, wd_h, wd_l, p_hid2, out, nullptr, nullptr, nullptr, HID, INTER);
}

// round 10
// speedup vs baseline: 1.0506x; 1.0506x over previous
#include <cuda_runtime.h>
#include <cuda_bf16.h>
#include <cstdint>
#include <math.h>

#define SEQ    3072
#define HID    1536
#define NH     12
#define HD     128
#define QKVW   4608   // 3*HID
#define INTER  13696
#define MAXL   1024
#define EPS    1e-6f

// ===================== PTX helpers (baseline PTX only) ======================
__device__ __forceinline__ uint32_t smem_to_u32(const void* p) {
    uint32_t a;
    asm("{ .reg .u64 t; cvta.to.shared.u64 t, %1; cvt.u32.u64 %0, t; }"
        : "=r"(a) : "l"(p));
    return a;
}
__device__ __forceinline__ void cp_async16(uint32_t dst, const void* src) {
    asm volatile("cp.async.cg.shared.global [%0], [%1], 16;"
                 :: "r"(dst), "l"(src) : "memory");
}
#define CP_COMMIT() asm volatile("cp.async.commit_group;" ::: "memory")
#define CP_WAIT1()  asm volatile("cp.async.wait_group 1;" ::: "memory")
#define CP_WAIT0()  asm volatile("cp.async.wait_group 0;" ::: "memory")

__device__ __forceinline__ void ldsm4(uint32_t* r, uint32_t addr) {
    asm volatile("ldmatrix.sync.aligned.m8n8.x4.shared.b16 {%0,%1,%2,%3}, [%4];"
                 : "=r"(r[0]), "=r"(r[1]), "=r"(r[2]), "=r"(r[3]) : "r"(addr));
}
__device__ __forceinline__ void ldsm2(uint32_t* r, uint32_t addr) {
    asm volatile("ldmatrix.sync.aligned.m8n8.x2.shared.b16 {%0,%1}, [%2];"
                 : "=r"(r[0]), "=r"(r[1]) : "r"(addr));
}
__device__ __forceinline__ void ldsm2t(uint32_t* r, uint32_t addr) {
    asm volatile("ldmatrix.sync.aligned.m8n8.x2.trans.shared.b16 {%0,%1}, [%2];"
                 : "=r"(r[0]), "=r"(r[1]) : "r"(addr));
}
__device__ __forceinline__ void mma_bf16(float* c, const uint32_t* a, const uint32_t* b) {
    asm volatile("mma.sync.aligned.m16n8k16.row.col.f32.bf16.bf16.f32 "
                 "{%0,%1,%2,%3}, {%4,%5,%6,%7}, {%8,%9}, {%0,%1,%2,%3};"
                 : "+f"(c[0]), "+f"(c[1]), "+f"(c[2]), "+f"(c[3])
                 : "r"(a[0]), "r"(a[1]), "r"(a[2]), "r"(a[3]),
                   "r"(b[0]), "r"(b[1]));
}
__device__ __forceinline__ void split_bf16(float v, __nv_bfloat16& h, __nv_bfloat16& l) {
    h = __float2bfloat16(v);
    l = __float2bfloat16(v - __bfloat162float(h));
}
__device__ __forceinline__ uint32_t sw128(uint32_t off) {
    return off ^ ((off >> 3) & 0x70);
}

// ===================== scratch =============================================
__device__ float g_qkv   [SEQ * QKVW];
__device__ float g_scores[(size_t)NH * SEQ * MAXL];
__device__ float g_hid2  [SEQ * HID];

__device__ __nv_bfloat16 g_hn_h [SEQ * HID],  g_hn_l [SEQ * HID];
__device__ __nv_bfloat16 g_h2n_h[SEQ * HID],  g_h2n_l[SEQ * HID];
__device__ __nv_bfloat16 g_at_h [SEQ * HID],  g_at_l [SEQ * HID];
__device__ __nv_bfloat16 g_act_h[(size_t)SEQ * INTER], g_act_l[(size_t)SEQ * INTER];

__device__ __nv_bfloat16 g_q_h[(size_t)NH * SEQ * HD], g_q_l[(size_t)NH * SEQ * HD];
__device__ __nv_bfloat16 g_k_h[(size_t)NH * SEQ * HD], g_k_l[(size_t)NH * SEQ * HD];
__device__ __nv_bfloat16 g_v_h[(size_t)NH * SEQ * HD], g_v_l[(size_t)NH * SEQ * HD];
__device__ __nv_bfloat16 g_p_h[(size_t)NH * SEQ * MAXL], g_p_l[(size_t)NH * SEQ * MAXL];

__device__ __nv_bfloat16 g_wqkv_h [(size_t)QKVW * HID],  g_wqkv_l [(size_t)QKVW * HID];
__device__ __nv_bfloat16 g_wproj_h[(size_t)HID * HID],   g_wproj_l[(size_t)HID * HID];
__device__ __nv_bfloat16 g_wgate_h[(size_t)INTER * HID], g_wgate_l[(size_t)INTER * HID];
__device__ __nv_bfloat16 g_wup_h  [(size_t)INTER * HID], g_wup_l  [(size_t)INTER * HID];
__device__ __nv_bfloat16 g_wdown_h[(size_t)HID * INTER], g_wdown_l[(size_t)HID * INTER];

// ===================== weight transpose + split =============================
__global__ void wconv_t(const float* __restrict__ W, __nv_bfloat16* __restrict__ Th,
                        __nv_bfloat16* __restrict__ Tl, int K, int N) {
    __shared__ float ts[32][33];
    int n0 = blockIdx.x * 32, k0 = blockIdx.y * 32;
    int tx = threadIdx.x, ty = threadIdx.y;   // 32 x 8
#pragma unroll
    for (int r = 0; r < 32; r += 8)
        ts[ty + r][tx] = W[(size_t)(k0 + ty + r) * N + n0 + tx];
    __syncthreads();
#pragma unroll
    for (int r = 0; r < 32; r += 8) {
        float v = ts[tx][ty + r];
        __nv_bfloat16 h, l;
        split_bf16(v, h, l);
        size_t o = (size_t)(n0 + ty + r) * K + k0 + tx;
        Th[o] = h;
        Tl[o] = l;
    }
}

// ===================== shared GEMM machinery (k=64 chunks) ==================
__device__ __forceinline__ void load_chunk(
    uint32_t buf, int tid,
    const __nv_bfloat16* __restrict__ Ah, const __nv_bfloat16* __restrict__ Al,
    const __nv_bfloat16* __restrict__ Bh, const __nv_bfloat16* __restrict__ Bl,
    int m0, int n0, int k0, int K) {
#pragma unroll
    for (int t = 0; t < 16; t++) {
        int idx = tid + t * 256;
        int tile = idx >> 10;
        int w = idx & 1023;
        int r = w >> 3, c8 = w & 7;
        const __nv_bfloat16* src =
            (tile == 0 ? Ah : tile == 1 ? Al : tile == 2 ? Bh : Bl);
        int row = (tile < 2 ? m0 : n0) + r;
        uint32_t dst = buf + tile * 16384 + sw128((uint32_t)(r * 128 + c8 * 16));
        cp_async16(dst, src + (size_t)row * K + k0 + c8 * 8);
    }
}

__device__ __forceinline__ void compute_chunk(
    uint32_t buf, int wm, int wn, int lane, float acc[4][4][4]) {
    const uint32_t bAh = buf;
    const uint32_t bAl = buf + 16384;
    const uint32_t bBh = buf + 32768;
    const uint32_t bBl = buf + 49152;
#pragma unroll
    for (int ks = 0; ks < 4; ks++) {
        uint32_t bh[4][2], bl[4][2];
#pragma unroll
        for (int ni = 0; ni < 4; ni++) {
            uint32_t rowB = wn * 32 + ni * 8 + (lane & 7);
            uint32_t kb = ks * 32 + ((lane >> 3) & 1) * 16;
            uint32_t sw = sw128(rowB * 128 + kb);
            ldsm2(bh[ni], bBh + sw);
            ldsm2(bl[ni], bBl + sw);
        }
#pragma unroll
        for (int mi = 0; mi < 4; mi++) {
            uint32_t rowA = wm * 64 + mi * 16 + (lane & 15);
            uint32_t kb = ks * 32 + (lane >> 4) * 16;
            uint32_t sw = sw128(rowA * 128 + kb);
            uint32_t ah[4], al[4];
            ldsm4(ah, bAh + sw);
            ldsm4(al, bAl + sw);
#pragma unroll
            for (int ni = 0; ni < 4; ni++) {
                mma_bf16(acc[mi][ni], ah, bh[ni]);
                mma_bf16(acc[mi][ni], ah, bl[ni]);
                mma_bf16(acc[mi][ni], al, bh[ni]);
            }
        }
    }
}

// ===================== main GEMM (fp32 out, optional residual) ==============
__global__ __launch_bounds__(256, 1) void gemm_bf16x3(
    const __nv_bfloat16* __restrict__ Ah, const __nv_bfloat16* __restrict__ Al,
    const __nv_bfloat16* __restrict__ Bh, const __nv_bfloat16* __restrict__ Bl,
    const float* __restrict__ R, float* __restrict__ C, int N, int K) {
    extern __shared__ char smem[];
    const uint32_t sb = smem_to_u32(smem);
    const int tid = threadIdx.x;
    const int wid = tid >> 5;
    const int lane = tid & 31;
    const int wm = wid & 1;
    const int wn = wid >> 1;
    const int m0 = blockIdx.x * 128;
    const int n0 = blockIdx.y * 128;

    float acc[4][4][4];
#pragma unroll
    for (int i = 0; i < 4; i++)
#pragma unroll
        for (int j = 0; j < 4; j++)
#pragma unroll
            for (int k = 0; k < 4; k++) acc[i][j][k] = 0.f;

    const int nch = K >> 6;
    load_chunk(sb, tid, Ah, Al, Bh, Bl, m0, n0, 0, K);
    CP_COMMIT();
    for (int i = 0; i < nch; i++) {
        if (i + 1 < nch) {
            load_chunk(sb + ((i + 1) & 1) * 65536, tid, Ah, Al, Bh, Bl,
                       m0, n0, (i + 1) << 6, K);
            CP_COMMIT();
            CP_WAIT1();
        } else {
            CP_WAIT0();
        }
        __syncthreads();
        compute_chunk(sb + (i & 1) * 65536, wm, wn, lane, acc);
        __syncthreads();
    }

    const int gr = lane >> 2;
    const int gc = (lane & 3) * 2;
#pragma unroll
    for (int mi = 0; mi < 4; mi++) {
        int r0 = m0 + wm * 64 + mi * 16 + gr;
#pragma unroll
        for (int ni = 0; ni < 4; ni++) {
            int c = n0 + wn * 32 + ni * 8 + gc;
            size_t o0 = (size_t)r0 * N + c;
            size_t o1 = (size_t)(r0 + 8) * N + c;
            float2 v0 = make_float2(acc[mi][ni][0], acc[mi][ni][1]);
            float2 v1 = make_float2(acc[mi][ni][2], acc[mi][ni][3]);
            if (R) {
                float2 rr0 = *(const float2*)(R + o0);
                float2 rr1 = *(const float2*)(R + o1);
                v0.x += rr0.x; v0.y += rr0.y;
                v1.x += rr1.x; v1.y += rr1.y;
            }
            *(float2*)(C + o0) = v0;
            *(float2*)(C + o1) = v1;
        }
    }
}

// ===================== fused gate+up+swiglu dual GEMM =======================
// stage: Ah@0, Al@16K, Gh@32K, Gl@48K, Uh@64K, Ul@80K ; 96KB/stage, 2 stages
#define DUAL_STAGE 98304
__device__ __forceinline__ void load_chunk_dual(
    uint32_t buf, int tid,
    const __nv_bfloat16* __restrict__ Ah, const __nv_bfloat16* __restrict__ Al,
    const __nv_bfloat16* __restrict__ Gh, const __nv_bfloat16* __restrict__ Gl,
    const __nv_bfloat16* __restrict__ Uh, const __nv_bfloat16* __restrict__ Ul,
    int m0, int n0, int k0, int K) {
#pragma unroll
    for (int t = 0; t < 24; t++) {
        int idx = tid + t * 256;            // 0..6143
        int tile = idx >> 10;               // 0..5
        int w = idx & 1023;
        int r = w >> 3, c8 = w & 7;
        const __nv_bfloat16* src =
            (tile == 0 ? Ah : tile == 1 ? Al : tile == 2 ? Gh :
             tile == 3 ? Gl : tile == 4 ? Uh : Ul);
        int row = (tile < 2 ? m0 : n0) + r;
        uint32_t dst = buf + tile * 16384 + sw128((uint32_t)(r * 128 + c8 * 16));
        cp_async16(dst, src + (size_t)row * K + k0 + c8 * 8);
    }
}

__global__ __launch_bounds__(256, 1) void gemm_swiglu_dual(
    const __nv_bfloat16* __restrict__ Ah, const __nv_bfloat16* __restrict__ Al,
    const __nv_bfloat16* __restrict__ Gh, const __nv_bfloat16* __restrict__ Gl,
    const __nv_bfloat16* __restrict__ Uh, const __nv_bfloat16* __restrict__ Ul,
    __nv_bfloat16* __restrict__ Oh, __nv_bfloat16* __restrict__ Ol,
    int N, int K) {
    extern __shared__ char smem[];
    const uint32_t sb = smem_to_u32(smem);
    const int tid = threadIdx.x;
    const int wid = tid >> 5;
    const int lane = tid & 31;
    const int wm = wid & 1;
    const int wn = wid >> 1;
    const int m0 = blockIdx.x * 128;
    const int n0 = blockIdx.y * 128;

    float ag[4][4][4], au[4][4][4];
#pragma unroll
    for (int i = 0; i < 4; i++)
#pragma unroll
        for (int j = 0; j < 4; j++)
#pragma unroll
            for (int k = 0; k < 4; k++) { ag[i][j][k] = 0.f; au[i][j][k] = 0.f; }

    const int nch = K >> 6;
    load_chunk_dual(sb, tid, Ah, Al, Gh, Gl, Uh, Ul, m0, n0, 0, K);
    CP_COMMIT();
    for (int i = 0; i < nch; i++) {
        if (i + 1 < nch) {
            load_chunk_dual(sb + ((i + 1) & 1) * DUAL_STAGE, tid,
                            Ah, Al, Gh, Gl, Uh, Ul, m0, n0, (i + 1) << 6, K);
            CP_COMMIT();
            CP_WAIT1();
        } else {
            CP_WAIT0();
        }
        __syncthreads();
        {
            const uint32_t buf = sb + (i & 1) * DUAL_STAGE;
            const uint32_t bAh = buf;
            const uint32_t bAl = buf + 16384;
            const uint32_t bGh = buf + 32768;
            const uint32_t bGl = buf + 49152;
            const uint32_t bUh = buf + 65536;
            const uint32_t bUl = buf + 81920;
#pragma unroll
            for (int ks = 0; ks < 4; ks++) {
                uint32_t gh[4][2], gl[4][2], uh[4][2], ul[4][2];
#pragma unroll
                for (int ni = 0; ni < 4; ni++) {
                    uint32_t rowB = wn * 32 + ni * 8 + (lane & 7);
                    uint32_t kb = ks * 32 + ((lane >> 3) & 1) * 16;
                    uint32_t sw = sw128(rowB * 128 + kb);
                    ldsm2(gh[ni], bGh + sw);
                    ldsm2(gl[ni], bGl + sw);
                    ldsm2(uh[ni], bUh + sw);
                    ldsm2(ul[ni], bUl + sw);
                }
#pragma unroll
                for (int mi = 0; mi < 4; mi++) {
                    uint32_t rowA = wm * 64 + mi * 16 + (lane & 15);
                    uint32_t kb = ks * 32 + (lane >> 4) * 16;
                    uint32_t sw = sw128(rowA * 128 + kb);
                    uint32_t ah[4], al[4];
                    ldsm4(ah, bAh + sw);
                    ldsm4(al, bAl + sw);
#pragma unroll
                    for (int ni = 0; ni < 4; ni++) {
                        mma_bf16(ag[mi][ni], ah, gh[ni]);
                        mma_bf16(ag[mi][ni], ah, gl[ni]);
                        mma_bf16(ag[mi][ni], al, gh[ni]);
                        mma_bf16(au[mi][ni], ah, uh[ni]);
                        mma_bf16(au[mi][ni], ah, ul[ni]);
                        mma_bf16(au[mi][ni], al, uh[ni]);
                    }
                }
            }
        }
        __syncthreads();
    }

    const int gr = lane >> 2;
    const int gc = (lane & 3) * 2;
#pragma unroll
    for (int mi = 0; mi < 4; mi++) {
        int r0 = m0 + wm * 64 + mi * 16 + gr;
#pragma unroll
        for (int ni = 0; ni < 4; ni++) {
            int c = n0 + wn * 32 + ni * 8 + gc;
            size_t o0 = (size_t)r0 * N + c;
            size_t o1 = (size_t)(r0 + 8) * N + c;
            float g, u, v;
            __nv_bfloat16 h, l;
            g = ag[mi][ni][0]; u = au[mi][ni][0];
            v = (g / (1.f + expf(-g))) * u;
            split_bf16(v, h, l); Oh[o0] = h; Ol[o0] = l;
            g = ag[mi][ni][1]; u = au[mi][ni][1];
            v = (g / (1.f + expf(-g))) * u;
            split_bf16(v, h, l); Oh[o0 + 1] = h; Ol[o0 + 1] = l;
            g = ag[mi][ni][2]; u = au[mi][ni][2];
            v = (g / (1.f + expf(-g))) * u;
            split_bf16(v, h, l); Oh[o1] = h; Ol[o1] = l;
            g = ag[mi][ni][3]; u = au[mi][ni][3];
            v = (g / (1.f + expf(-g))) * u;
            split_bf16(v, h, l); Oh[o1 + 1] = h; Ol[o1 + 1] = l;
        }
    }
}

// ===================== attention QK^T =======================================
__global__ __launch_bounds__(256, 1) void attn_qk(
    const __nv_bfloat16* __restrict__ Qh, const __nv_bfloat16* __restrict__ Ql,
    const __nv_bfloat16* __restrict__ Kh, const __nv_bfloat16* __restrict__ Kl,
    const int* __restrict__ cu, int nseg, float* __restrict__ scores) {
    extern __shared__ char smem[];
    const uint32_t sb = smem_to_u32(smem);
    const int h = blockIdx.z / nseg, s = blockIdx.z % nseg;
    const int s0 = cu[s];
    const int L = cu[s + 1] - s0;
    const int q0 = blockIdx.y * 128, kt0 = blockIdx.x * 128;
    if (q0 >= L || kt0 >= L) return;
    const int tid = threadIdx.x;
    const int wid = tid >> 5, lane = tid & 31;
    const int wm = wid & 1, wn = wid >> 1;

    const __nv_bfloat16* qh = Qh + ((size_t)h * SEQ + s0 + q0) * HD;
    const __nv_bfloat16* ql = Ql + ((size_t)h * SEQ + s0 + q0) * HD;
    const __nv_bfloat16* kh = Kh + ((size_t)h * SEQ + s0 + kt0) * HD;
    const __nv_bfloat16* kl = Kl + ((size_t)h * SEQ + s0 + kt0) * HD;

    float acc[4][4][4];
#pragma unroll
    for (int i = 0; i < 4; i++)
#pragma unroll
        for (int j = 0; j < 4; j++)
#pragma unroll
            for (int k = 0; k < 4; k++) acc[i][j][k] = 0.f;

    load_chunk(sb, tid, qh, ql, kh, kl, 0, 0, 0, HD);
    CP_COMMIT();
    for (int i = 0; i < 2; i++) {
        if (i == 0) {
            load_chunk(sb + 65536, tid, qh, ql, kh, kl, 0, 0, 64, HD);
            CP_COMMIT();
            CP_WAIT1();
        } else {
            CP_WAIT0();
        }
        __syncthreads();
        compute_chunk(sb + i * 65536, wm, wn, lane, acc);
        __syncthreads();
    }

    const float scale = 0.088388347648318447f;
    const int gr = lane >> 2;
    const int gc = (lane & 3) * 2;
#pragma unroll
    for (int mi = 0; mi < 4; mi++) {
        int qg = s0 + q0 + wm * 64 + mi * 16 + gr;
#pragma unroll
        for (int ni = 0; ni < 4; ni++) {
            int c = kt0 + wn * 32 + ni * 8 + gc;
            size_t o0 = ((size_t)h * SEQ + qg) * MAXL + c;
            size_t o1 = ((size_t)h * SEQ + qg + 8) * MAXL + c;
            *(float2*)(scores + o0) =
                make_float2(acc[mi][ni][0] * scale, acc[mi][ni][1] * scale);
            *(float2*)(scores + o1) =
                make_float2(acc[mi][ni][2] * scale, acc[mi][ni][3] * scale);
        }
    }
}

// ===================== softmax -> P hi/lo bf16 ==============================
__global__ void softmax_psplit(float* __restrict__ scores,
                               const int* __restrict__ cu, int nseg,
                               __nv_bfloat16* __restrict__ ph,
                               __nv_bfloat16* __restrict__ pl) {
    int row = blockIdx.x;
    int q = row % SEQ;
    int L = MAXL;
    for (int s = 0; s < nseg; s++)
        if (q >= cu[s] && q < cu[s + 1]) { L = cu[s + 1] - cu[s]; break; }
    float* r = scores + (size_t)row * MAXL;
    int tid = threadIdx.x;
    __shared__ float red[256];
    float m = -3.4e38f;
    for (int i = tid; i < L; i += 256) m = fmaxf(m, r[i]);
    red[tid] = m;
    __syncthreads();
    for (int s = 128; s > 0; s >>= 1) {
        if (tid < s) red[tid] = fmaxf(red[tid], red[tid + s]);
        __syncthreads();
    }
    m = red[0];
    __syncthreads();
    float sum = 0.f;
    for (int i = tid; i < L; i += 256) {
        float e = expf(r[i] - m);
        r[i] = e;
        sum += e;
    }
    red[tid] = sum;
    __syncthreads();
    for (int s = 128; s > 0; s >>= 1) {
        if (tid < s) red[tid] += red[tid + s];
        __syncthreads();
    }
    float inv = 1.f / red[0];
    for (int i = tid; i < L; i += 256) {
        float p = r[i] * inv;
        __nv_bfloat16 hh, ll;
        split_bf16(p, hh, ll);
        ph[(size_t)row * MAXL + i] = hh;
        pl[(size_t)row * MAXL + i] = ll;
    }
}

// ===================== attention P@V ========================================
__device__ __forceinline__ void load_chunk_pv(
    uint32_t buf, int tid,
    const __nv_bfloat16* __restrict__ Ph, const __nv_bfloat16* __restrict__ Pl,
    const __nv_bfloat16* __restrict__ Vh, const __nv_bfloat16* __restrict__ Vl,
    int k0) {
#pragma unroll
    for (int t = 0; t < 16; t++) {
        int idx = tid + t * 256;
        int tile = idx >> 10;
        int w = idx & 1023;
        if (tile < 2) {
            int r = w >> 3, c8 = w & 7;
            const __nv_bfloat16* src = (tile == 0) ? Ph : Pl;
            uint32_t dst = buf + tile * 16384 + sw128((uint32_t)(r * 128 + c8 * 16));
            cp_async16(dst, src + (size_t)r * MAXL + k0 + c8 * 8);
        } else {
            int r = w >> 4, c = w & 15;
            const __nv_bfloat16* src = (tile == 2) ? Vh : Vl;
            uint32_t dst = buf + 32768 + (tile - 2) * 16384 +
                           sw128((uint32_t)(r * 256 + c * 16));
            cp_async16(dst, src + (size_t)(k0 + r) * HD + c * 8);
        }
    }
}

__global__ __launch_bounds__(256, 1) void attn_pv_mma(
    const __nv_bfloat16* __restrict__ Ph, const __nv_bfloat16* __restrict__ Pl,
    const __nv_bfloat16* __restrict__ Vh, const __nv_bfloat16* __restrict__ Vl,
    const int* __restrict__ cu, int nseg,
    __nv_bfloat16* __restrict__ oh, __nv_bfloat16* __restrict__ ol) {
    extern __shared__ char smem[];
    const uint32_t sb = smem_to_u32(smem);
    const int h = blockIdx.z / nseg, s = blockIdx.z % nseg;
    const int s0 = cu[s];
    const int L = cu[s + 1] - s0;
    const int q0 = blockIdx.y * 128;
    if (q0 >= L) return;
    const int tid = threadIdx.x;
    const int wid = tid >> 5, lane = tid & 31;
    const int wm = wid & 1, wn = wid >> 1;

    const __nv_bfloat16* ph = Ph + ((size_t)h * SEQ + s0 + q0) * MAXL;
    const __nv_bfloat16* pl = Pl + ((size_t)h * SEQ + s0 + q0) * MAXL;
    const __nv_bfloat16* vh = Vh + ((size_t)h * SEQ + s0) * HD;
    const __nv_bfloat16* vl = Vl + ((size_t)h * SEQ + s0) * HD;

    float acc[4][4][4];
#pragma unroll
    for (int i = 0; i < 4; i++)
#pragma unroll
        for (int j = 0; j < 4; j++)
#pragma unroll
            for (int k = 0; k < 4; k++) acc[i][j][k] = 0.f;

    const int nch = L >> 6;
    load_chunk_pv(sb, tid, ph, pl, vh, vl, 0);
    CP_COMMIT();
    for (int i = 0; i < nch; i++) {
        if (i + 1 < nch) {
            load_chunk_pv(sb + ((i + 1) & 1) * 65536, tid, ph, pl, vh, vl, (i + 1) << 6);
            CP_COMMIT();
            CP_WAIT1();
        } else {
            CP_WAIT0();
        }
        __syncthreads();
        {
            const uint32_t buf = sb + (i & 1) * 65536;
            const uint32_t bAh = buf;
            const uint32_t bAl = buf + 16384;
            const uint32_t bBh = buf + 32768;
            const uint32_t bBl = buf + 49152;
#pragma unroll
            for (int ks = 0; ks < 4; ks++) {
                uint32_t bh[4][2], bl[4][2];
#pragma unroll
                for (int ni = 0; ni < 4; ni++) {
                    uint32_t nb = (wn * 32 + ni * 8) * 2;
                    uint32_t sw = sw128((ks * 16 + (lane & 15)) * 256 + nb);
                    ldsm2t(bh[ni], bBh + sw);
                    ldsm2t(bl[ni], bBl + sw);
                }
#pragma unroll
                for (int mi = 0; mi < 4; mi++) {
                    uint32_t rowA = wm * 64 + mi * 16 + (lane & 15);
                    uint32_t kb = ks * 32 + (lane >> 4) * 16;
                    uint32_t sw = sw128(rowA * 128 + kb);
                    uint32_t ah[4], al[4];
                    ldsm4(ah, bAh + sw);
                    ldsm4(al, bAl + sw);
#pragma unroll
                    for (int ni = 0; ni < 4; ni++) {
                        mma_bf16(acc[mi][ni], ah, bh[ni]);
                        mma_bf16(acc[mi][ni], ah, bl[ni]);
                        mma_bf16(acc[mi][ni], al, bh[ni]);
                    }
                }
            }
        }
        __syncthreads();
    }

    const int gr = lane >> 2;
    const int gc = (lane & 3) * 2;
#pragma unroll
    for (int mi = 0; mi < 4; mi++) {
        int qg = s0 + q0 + wm * 64 + mi * 16 + gr;
#pragma unroll
        for (int ni = 0; ni < 4; ni++) {
            int d = wn * 32 + ni * 8 + gc;
            size_t o0 = (size_t)qg * HID + h * HD + d;
            size_t o1 = (size_t)(qg + 8) * HID + h * HD + d;
            __nv_bfloat16 hh, ll;
            split_bf16(acc[mi][ni][0], hh, ll); oh[o0] = hh; ol[o0] = ll;
            split_bf16(acc[mi][ni][1], hh, ll); oh[o0 + 1] = hh; ol[o0 + 1] = ll;
            split_bf16(acc[mi][ni][2], hh, ll); oh[o1] = hh; ol[o1] = ll;
            split_bf16(acc[mi][ni][3], hh, ll); oh[o1 + 1] = hh; ol[o1 + 1] = ll;
        }
    }
}

// ===================== RMSNorm -> bf16 hi/lo ================================
__global__ void rmsnorm_split(const float* __restrict__ x, const float* __restrict__ w,
                              __nv_bfloat16* __restrict__ yh, __nv_bfloat16* __restrict__ yl) {
    int row = blockIdx.x;
    const float* xr = x + (size_t)row * HID;
    int tid = threadIdx.x;
    float ss = 0.f;
    for (int i = tid; i < HID; i += 256) { float v = xr[i]; ss += v * v; }
    __shared__ float red[256];
    red[tid] = ss;
    __syncthreads();
    for (int s = 128; s > 0; s >>= 1) {
        if (tid < s) red[tid] += red[tid + s];
        __syncthreads();
    }
    float inv = rsqrtf(red[0] / (float)HID + EPS);
    for (int i = tid; i < HID; i += 256) {
        float v = xr[i] * inv * w[i];
        __nv_bfloat16 h, l;
        split_bf16(v, h, l);
        yh[(size_t)row * HID + i] = h;
        yl[(size_t)row * HID + i] = l;
    }
}

// ===================== RoPE + per-head split ================================
__global__ void rope_split(const float* __restrict__ qkv, const float* __restrict__ rot,
                           __nv_bfloat16* __restrict__ qh, __nv_bfloat16* __restrict__ ql,
                           __nv_bfloat16* __restrict__ kh, __nv_bfloat16* __restrict__ kl,
                           __nv_bfloat16* __restrict__ vh, __nv_bfloat16* __restrict__ vl) {
    int n = blockIdx.x, h = blockIdx.y, d = threadIdx.x;
    float ang = rot[n * HD + d];
    float c = cosf(ang), s = sinf(ang);
    const float* q = qkv + (size_t)n * QKVW + h * HD;
    const float* k = q + HID;
    const float* v = q + 2 * HID;
    int p = (d < 64) ? d + 64 : d - 64;
    float sgn = (d < 64) ? -1.f : 1.f;
    float qr = q[d] * c + sgn * q[p] * s;
    float kr = k[d] * c + sgn * k[p] * s;
    float vv = v[d];
    size_t o = ((size_t)h * SEQ + n) * HD + d;
    __nv_bfloat16 hh, ll;
    split_bf16(qr, hh, ll); qh[o] = hh; ql[o] = ll;
    split_bf16(kr, hh, ll); kh[o] = hh; kl[o] = ll;
    split_bf16(vv, hh, ll); vh[o] = hh; vl[o] = ll;
}

// ===================== host orchestration ===================================
extern "C" void kernel_launch(void* const* d_in, const int* in_sizes, int n_in,
                              void* d_out, int out_size) {
    const float* hidden = (const float*)d_in[0];
    const float* rot    = (const float*)d_in[1];
    const float* n1w    = (const float*)d_in[2];
    const float* n2w    = (const float*)d_in[3];
    const float* qkv_w  = (const float*)d_in[4];
    const float* proj_w = (const float*)d_in[5];
    const float* gate_w = (const float*)d_in[6];
    const float* up_w   = (const float*)d_in[7];
    const float* down_w = (const float*)d_in[8];
    const int*   cu     = (const int*)d_in[9];
    float* out = (float*)d_out;
    int nseg = in_sizes[9] - 1;

    const int GEMM_SMEM = 2 * 65536;
    const int DUAL_SMEM = 2 * DUAL_STAGE;
    cudaFuncSetAttribute(gemm_bf16x3, cudaFuncAttributeMaxDynamicSharedMemorySize, GEMM_SMEM);
    cudaFuncSetAttribute(gemm_swiglu_dual, cudaFuncAttributeMaxDynamicSharedMemorySize, DUAL_SMEM);
    cudaFuncSetAttribute(attn_qk, cudaFuncAttributeMaxDynamicSharedMemorySize, GEMM_SMEM);
    cudaFuncSetAttribute(attn_pv_mma, cudaFuncAttributeMaxDynamicSharedMemorySize, GEMM_SMEM);

    float *p_qkv, *p_scores, *p_hid2;
    cudaGetSymbolAddress((void**)&p_qkv,    g_qkv);
    cudaGetSymbolAddress((void**)&p_scores, g_scores);
    cudaGetSymbolAddress((void**)&p_hid2,   g_hid2);
    __nv_bfloat16 *hn_h, *hn_l, *h2n_h, *h2n_l, *at_h, *at_l, *act_h, *act_l;
    __nv_bfloat16 *q_h, *q_l, *k_h, *k_l, *v_h, *v_l, *pp_h, *pp_l;
    __nv_bfloat16 *wq_h, *wq_l, *wp_h, *wp_l, *wg_h, *wg_l, *wu_h, *wu_l, *wd_h, *wd_l;
    cudaGetSymbolAddress((void**)&hn_h, g_hn_h);   cudaGetSymbolAddress((void**)&hn_l, g_hn_l);
    cudaGetSymbolAddress((void**)&h2n_h, g_h2n_h); cudaGetSymbolAddress((void**)&h2n_l, g_h2n_l);
    cudaGetSymbolAddress((void**)&at_h, g_at_h);   cudaGetSymbolAddress((void**)&at_l, g_at_l);
    cudaGetSymbolAddress((void**)&act_h, g_act_h); cudaGetSymbolAddress((void**)&act_l, g_act_l);
    cudaGetSymbolAddress((void**)&q_h, g_q_h);     cudaGetSymbolAddress((void**)&q_l, g_q_l);
    cudaGetSymbolAddress((void**)&k_h, g_k_h);     cudaGetSymbolAddress((void**)&k_l, g_k_l);
    cudaGetSymbolAddress((void**)&v_h, g_v_h);     cudaGetSymbolAddress((void**)&v_l, g_v_l);
    cudaGetSymbolAddress((void**)&pp_h, g_p_h);    cudaGetSymbolAddress((void**)&pp_l, g_p_l);
    cudaGetSymbolAddress((void**)&wq_h, g_wqkv_h); cudaGetSymbolAddress((void**)&wq_l, g_wqkv_l);
    cudaGetSymbolAddress((void**)&wp_h, g_wproj_h);cudaGetSymbolAddress((void**)&wp_l, g_wproj_l);
    cudaGetSymbolAddress((void**)&wg_h, g_wgate_h);cudaGetSymbolAddress((void**)&wg_l, g_wgate_l);
    cudaGetSymbolAddress((void**)&wu_h, g_wup_h);  cudaGetSymbolAddress((void**)&wu_l, g_wup_l);
    cudaGetSymbolAddress((void**)&wd_h, g_wdown_h);cudaGetSymbolAddress((void**)&wd_l, g_wdown_l);

    dim3 tb(32, 8);
    wconv_t<<<dim3(QKVW / 32, HID / 32), tb>>>(qkv_w, wq_h, wq_l, HID, QKVW);
    wconv_t<<<dim3(HID / 32, HID / 32), tb>>>(proj_w, wp_h, wp_l, HID, HID);
    wconv_t<<<dim3(INTER / 32, HID / 32), tb>>>(gate_w, wg_h, wg_l, HID, INTER);
    wconv_t<<<dim3(INTER / 32, HID / 32), tb>>>(up_w, wu_h, wu_l, HID, INTER);
    wconv_t<<<dim3(HID / 32, INTER / 32), tb>>>(down_w, wd_h, wd_l, INTER, HID);

    // 1. norm1
    rmsnorm_split<<<SEQ, 256>>>(hidden, n1w, hn_h, hn_l);
    // 2. qkv
    gemm_bf16x3<<<dim3(SEQ / 128, QKVW / 128), 256, GEMM_SMEM>>>(
        hn_h, hn_l, wq_h, wq_l, nullptr, p_qkv, QKVW, HID);
    // 3. rope + per-head bf16 split
    rope_split<<<dim3(SEQ, NH), HD>>>(p_qkv, rot, q_h, q_l, k_h, k_l, v_h, v_l);
    // 4. scores (tensor core)
    attn_qk<<<dim3(MAXL / 128, MAXL / 128, NH * nseg), 256, GEMM_SMEM>>>(
        q_h, q_l, k_h, k_l, cu, nseg, p_scores);
    // 5. softmax -> P hi/lo
    softmax_psplit<<<NH * SEQ, 256>>>(p_scores, cu, nseg, pp_h, pp_l);
    // 6. O = P @ V
    attn_pv_mma<<<dim3(1, MAXL / 128, NH * nseg), 256, GEMM_SMEM>>>(
        pp_h, pp_l, v_h, v_l, cu, nseg, at_h, at_l);
    // 7. hid2 = attn @ proj_w + hidden
    gemm_bf16x3<<<dim3(SEQ / 128, HID / 128), 256, GEMM_SMEM>>>(
        at_h, at_l, wp_h, wp_l, hidden, p_hid2, HID, HID);
    // 8. norm2
    rmsnorm_split<<<SEQ, 256>>>(p_hid2, n2w, h2n_h, h2n_l);
    // 9. fused gate+up+swiglu -> act hi/lo (one pass over A, both weights)
    gemm_swiglu_dual<<<dim3(SEQ / 128, INTER / 128), 256, DUAL_SMEM>>>(
        h2n_h, h2n_l, wg_h, wg_l, wu_h, wu_l, act_h, act_l, INTER, HID);
    // 10. out = act @ down_w + hid2
    gemm_bf16x3<<<dim3(SEQ / 128, HID / 128), 256, GEMM_SMEM>>>(
        act_h, act_l, wd_h, wd_l, p_hid2, out, HID, INTER);
}